// round 2
// baseline (speedup 1.0000x reference)
#include <cuda_runtime.h>

#define LATENT  10
#define MAXLEN  80
#define BATCH   512
#define NSTEPS  100
#define HID     64
#define DTC     0.01f

typedef unsigned long long u64;

// ---------------- packed f32x2 helpers (sm_100+) ----------------
__device__ __forceinline__ u64 pk(float x, float y) {
    u64 r;
    asm("mov.b64 %0, {%1, %2};" : "=l"(r) : "f"(x), "f"(y));
    return r;
}
__device__ __forceinline__ void upk(u64 a, float& x, float& y) {
    asm("mov.b64 {%0, %1}, %2;" : "=f"(x), "=f"(y) : "l"(a));
}
__device__ __forceinline__ u64 fma2_(u64 a, u64 b, u64 c) {
    u64 d;
    asm("fma.rn.f32x2 %0, %1, %2, %3;" : "=l"(d) : "l"(a), "l"(b), "l"(c));
    return d;
}
__device__ __forceinline__ u64 mul2_(u64 a, u64 b) {
    u64 d;
    asm("mul.rn.f32x2 %0, %1, %2;" : "=l"(d) : "l"(a), "l"(b));
    return d;
}
__device__ __forceinline__ u64 sub2_(u64 a, u64 b) {
    u64 d;
    asm("sub.rn.f32x2 %0, %1, %2;" : "=l"(d) : "l"(a), "l"(b));
    return d;
}

struct Chain {
    u64 xt[5], mu2[5], sinv2[5], hv2[5], ssd2[5], err2[5];
};

__device__ __forceinline__ void init_chain(Chain& c, const float* __restrict__ zmr,
                                           const float* __restrict__ zvr, int l)
{
#pragma unroll
    for (int p = 0; p < 5; p++) {
        float muv[2], siv[2], hvv[2], ssv[2];
#pragma unroll
        for (int q = 0; q < 2; q++) {
            int d = 2 * p + q;
            float zmc = zmr[d];
            float zmp = (l > 0) ? zmr[d - LATENT] : 0.0f;
            float mu  = zmc - zmp;
            float a_  = (l > 0) ? zvr[d - LATENT] : 0.0f;
            float bb  = zvr[d];
            float mx  = fmaxf(a_, bb);
            float sg  = mx + log1pf(expf(-fabsf(a_ - bb)));   // logaddexp
            float sstd = expf(0.5f * sg);
            float svar = sstd * sstd;
            muv[q] = mu;
            siv[q] = 1.0f / sg;            // logdx = (mu - xt) / sigma
            hvv[q] = 0.5f * svar * DTC;    // drift score coefficient
            ssv[q] = sstd * 0.1f;          // sigma_std * sqrt(dt)
        }
        c.mu2[p]   = pk(muv[0], muv[1]);
        c.sinv2[p] = pk(siv[0], siv[1]);
        c.hv2[p]   = pk(hvv[0], hvv[1]);
        c.ssd2[p]  = pk(ssv[0], ssv[1]);
        c.xt[p]    = c.mu2[p];
        c.err2[p]  = pk(0.0f, 0.0f);
    }
}

__device__ __forceinline__ void write_chain(Chain& c, float* __restrict__ out, int b, int l)
{
    float2* o0 = (float2*)(out + ((size_t)b * MAXLEN + l) * LATENT);
    float2* o1 = (float2*)(out + (size_t)BATCH * MAXLEN * LATENT
                               + ((size_t)b * MAXLEN + l) * LATENT);
    const float inv_n = 1.0f / (float)NSTEPS;
#pragma unroll
    for (int p = 0; p < 5; p++) {
        float x, y;
        upk(c.xt[p], x, y);
        o0[p] = make_float2(x, y);
        upk(c.err2[p], x, y);
        o1[p] = make_float2(x * inv_n, y * inv_n);
    }
}

// Two chains per thread, both at the same position l (shared weights, shared t).
__global__ void __launch_bounds__(128)
vae_sde2_kernel(const float* __restrict__ zm,
                const float* __restrict__ zlv,
                const float* __restrict__ W1,
                const float* __restrict__ b1,
                const float* __restrict__ W2,
                const float* __restrict__ b2,
                const float* __restrict__ noise,
                float* __restrict__ out)
{
    __shared__ __align__(16) float sW1f[HID * 12];
    __shared__ __align__(16) float sW2f[HID * 12];

    const int tid = threadIdx.x;
    for (int i = tid; i < HID * 12; i += 128) {
        int j = i / 12, k = i % 12;
        sW1f[i] = (k < 11) ? W1[k * HID + j] : b1[j];
        sW2f[i] = (k < 10) ? W2[j * 10 + k] : 0.0f;
    }
    __syncthreads();

    const ulonglong2* sW1v = (const ulonglong2*)sW1f;
    const ulonglong2* sW2v = (const ulonglong2*)sW2f;
    const u64*        sW2u = (const u64*)sW2f;

    const int T  = blockIdx.x * 128 + tid;       // 0..20479
    const int l  = T >> 8;                       // position 0..79
    const int bA = T & 255;                      // batch 0..255
    const int bB = bA + 256;                     // batch 256..511

    u64 b2r[5];
#pragma unroll
    for (int p = 0; p < 5; p++) b2r[p] = pk(b2[2*p], b2[2*p+1]);

    Chain cA, cB;
    init_chain(cA, zm + ((size_t)bA * MAXLEN + l) * LATENT,
                   zlv + ((size_t)bA * MAXLEN + l) * LATENT, l);
    init_chain(cB, zm + ((size_t)bB * MAXLEN + l) * LATENT,
                   zlv + ((size_t)bB * MAXLEN + l) * LATENT, l);

    const u64 dt2 = pk(DTC, DTC);

    const u64* nzA = (const u64*)(noise + ((size_t)l * NSTEPS * BATCH + bA) * LATENT);
    const u64* nzB = (const u64*)(noise + ((size_t)l * NSTEPS * BATCH + bB) * LATENT);
    const int  nz_stride = BATCH * LATENT / 2;

    for (int s = 0; s < NSTEPS; s++) {
        u64 scA[5], scB[5];
#pragma unroll
        for (int p = 0; p < 5; p++) { scA[p] = b2r[p]; scB[p] = b2r[p]; }

        const float t = (float)(l + s) * DTC;
        const u64 f5 = pk(t, 1.0f);

#pragma unroll 4
        for (int j = 0; j < HID; j++) {
            ulonglong2 a0 = sW1v[j * 3 + 0];
            ulonglong2 a1 = sW1v[j * 3 + 1];
            ulonglong2 a2 = sW1v[j * 3 + 2];

            u64 accA = mul2_(cA.xt[0], a0.x);
            u64 accB = mul2_(cB.xt[0], a0.x);
            accA = fma2_(cA.xt[1], a0.y, accA);
            accB = fma2_(cB.xt[1], a0.y, accB);
            accA = fma2_(cA.xt[2], a1.x, accA);
            accB = fma2_(cB.xt[2], a1.x, accB);
            accA = fma2_(cA.xt[3], a1.y, accA);
            accB = fma2_(cB.xt[3], a1.y, accB);
            accA = fma2_(cA.xt[4], a2.x, accA);
            accB = fma2_(cB.xt[4], a2.x, accB);
            accA = fma2_(f5, a2.y, accA);
            accB = fma2_(f5, a2.y, accB);

            float al, ah, bl, bh;
            upk(accA, al, ah);
            upk(accB, bl, bh);
            float hA = fmaxf(al + ah, 0.0f);
            float hB = fmaxf(bl + bh, 0.0f);
            u64 hdA = pk(hA, hA);
            u64 hdB = pk(hB, hB);

            ulonglong2 c0 = sW2v[j * 3 + 0];
            ulonglong2 c1 = sW2v[j * 3 + 1];
            u64        c2 = sW2u[j * 6 + 4];

            scA[0] = fma2_(hdA, c0.x, scA[0]);
            scB[0] = fma2_(hdB, c0.x, scB[0]);
            scA[1] = fma2_(hdA, c0.y, scA[1]);
            scB[1] = fma2_(hdB, c0.y, scB[1]);
            scA[2] = fma2_(hdA, c1.x, scA[2]);
            scB[2] = fma2_(hdB, c1.x, scB[2]);
            scA[3] = fma2_(hdA, c1.y, scA[3]);
            scB[3] = fma2_(hdB, c1.y, scB[3]);
            scA[4] = fma2_(hdA, c2,   scA[4]);
            scB[4] = fma2_(hdB, c2,   scB[4]);
        }

        // elementwise SDE update + score error, both chains
#pragma unroll
        for (int p = 0; p < 5; p++) {
            u64 nz    = nzA[p];
            u64 logdx = mul2_(sub2_(cA.mu2[p], cA.xt[p]), cA.sinv2[p]);
            u64 diff  = sub2_(logdx, scA[p]);
            cA.err2[p] = fma2_(diff, diff, cA.err2[p]);
            u64 x     = fma2_(cA.mu2[p], dt2, cA.xt[p]);
            x         = fma2_(scA[p], cA.hv2[p], x);
            cA.xt[p]  = fma2_(nz, cA.ssd2[p], x);
        }
#pragma unroll
        for (int p = 0; p < 5; p++) {
            u64 nz    = nzB[p];
            u64 logdx = mul2_(sub2_(cB.mu2[p], cB.xt[p]), cB.sinv2[p]);
            u64 diff  = sub2_(logdx, scB[p]);
            cB.err2[p] = fma2_(diff, diff, cB.err2[p]);
            u64 x     = fma2_(cB.mu2[p], dt2, cB.xt[p]);
            x         = fma2_(scB[p], cB.hv2[p], x);
            cB.xt[p]  = fma2_(nz, cB.ssd2[p], x);
        }
        nzA += nz_stride;
        nzB += nz_stride;
    }

    write_chain(cA, out, bA, l);
    write_chain(cB, out, bB, l);
}

extern "C" void kernel_launch(void* const* d_in, const int* in_sizes, int n_in,
                              void* d_out, int out_size)
{
    const float* zm    = (const float*)d_in[0];
    const float* zlv   = (const float*)d_in[1];
    const float* W1    = (const float*)d_in[2];
    const float* b1    = (const float*)d_in[3];
    const float* W2    = (const float*)d_in[4];
    const float* b2    = (const float*)d_in[5];
    const float* noise = (const float*)d_in[6];
    float* out = (float*)d_out;

    const int total = BATCH * MAXLEN / 2;        // 20480 threads, 2 chains each
    vae_sde2_kernel<<<total / 128, 128>>>(zm, zlv, W1, b1, W2, b2, noise, out);
}

// round 4
// speedup vs baseline: 1.3963x; 1.3963x over previous
#include <cuda_runtime.h>

#define LATENT  10
#define MAXLEN  80
#define BATCH   512
#define NSTEPS  100
#define HID     64
#define DTC     0.01f

typedef unsigned long long u64;

// ---------------- packed f32x2 helpers (sm_100+) ----------------
__device__ __forceinline__ u64 pk(float x, float y) {
    u64 r;
    asm("mov.b64 %0, {%1, %2};" : "=l"(r) : "f"(x), "f"(y));
    return r;
}
__device__ __forceinline__ void upk(u64 a, float& x, float& y) {
    asm("mov.b64 {%0, %1}, %2;" : "=f"(x), "=f"(y) : "l"(a));
}
__device__ __forceinline__ u64 fma2_(u64 a, u64 b, u64 c) {
    u64 d;
    asm("fma.rn.f32x2 %0, %1, %2, %3;" : "=l"(d) : "l"(a), "l"(b), "l"(c));
    return d;
}
__device__ __forceinline__ u64 mul2_(u64 a, u64 b) {
    u64 d;
    asm("mul.rn.f32x2 %0, %1, %2;" : "=l"(d) : "l"(a), "l"(b));
    return d;
}
__device__ __forceinline__ u64 sub2_(u64 a, u64 b) {
    u64 d;
    asm("sub.rn.f32x2 %0, %1, %2;" : "=l"(d) : "l"(a), "l"(b));
    return d;
}

// Weights packed over HIDDEN-UNIT PAIRS (jp = j/2):
//   sW1p[jp][k] = (W1[k][2jp], W1[k][2jp+1])   k=0..10, k=11 holds (b1[2jp], b1[2jp+1])
//   sW2p[jp][e] = (W2[2jp][e], W2[2jp+1][e])   e=0..9
// Layer 1: acc2[jp] = sum_k dup(x_k) * sW1p[jp][k]  -> both hidden units at once,
// relu is a packed max, and h2 (packed over j) feeds layer 2 fma2 directly.
__global__ void __launch_bounds__(32)
vae_sde3_kernel(const float* __restrict__ zm,
                const float* __restrict__ zlv,
                const float* __restrict__ W1,
                const float* __restrict__ b1,
                const float* __restrict__ W2,
                const float* __restrict__ b2,
                const float* __restrict__ noise,
                float* __restrict__ out)
{
    __shared__ __align__(16) u64 sW1p[32][12];   // 3072 B
    __shared__ __align__(16) u64 sW2p[32][10];   // 2560 B

    const int tid = threadIdx.x;      // 0..31 (one warp per CTA)

    // stage weights (32 threads, one jp each)
    {
        int jp = tid;
        int j0 = 2 * jp, j1 = 2 * jp + 1;
#pragma unroll
        for (int k = 0; k < 11; k++)
            sW1p[jp][k] = pk(W1[k * HID + j0], W1[k * HID + j1]);
        sW1p[jp][11] = pk(b1[j0], b1[j1]);
#pragma unroll
        for (int e = 0; e < 10; e++)
            sW2p[jp][e] = pk(W2[j0 * 10 + e], W2[j1 * 10 + e]);
    }
    __syncwarp();

    const int T = blockIdx.x * 32 + tid;       // chain id < 40960
    const int l = T >> 9;                      // position (uniform per warp)
    const int b = T & 511;

    // b2 halves for layer-2 accumulator init: sc2[e] starts at (b2[e], 0)
    u64 b2h[10];
#pragma unroll
    for (int e = 0; e < 10; e++) b2h[e] = pk(b2[e], 0.0f);

    // ---- per-chain precompute ----
    const float* zmr = zm  + ((size_t)b * MAXLEN + l) * LATENT;
    const float* zvr = zlv + ((size_t)b * MAXLEN + l) * LATENT;

    u64 xt[5], mu2[5], sinv2[5], hv2[5], ssd2[5], err2[5];
#pragma unroll
    for (int p = 0; p < 5; p++) {
        float muv[2], siv[2], hvv[2], ssv[2];
#pragma unroll
        for (int q = 0; q < 2; q++) {
            int d = 2 * p + q;
            float zmc = zmr[d];
            float zmp = (l > 0) ? zmr[d - LATENT] : 0.0f;
            float mu  = zmc - zmp;
            float a_  = (l > 0) ? zvr[d - LATENT] : 0.0f;
            float bb  = zvr[d];
            float mx  = fmaxf(a_, bb);
            float sg  = mx + log1pf(expf(-fabsf(a_ - bb)));   // logaddexp
            float sstd = expf(0.5f * sg);
            float svar = sstd * sstd;
            muv[q] = mu;
            siv[q] = 1.0f / sg;
            hvv[q] = 0.5f * svar * DTC;
            ssv[q] = sstd * 0.1f;          // sigma_std * sqrt(dt)
        }
        mu2[p]   = pk(muv[0], muv[1]);
        sinv2[p] = pk(siv[0], siv[1]);
        hv2[p]   = pk(hvv[0], hvv[1]);
        ssd2[p]  = pk(ssv[0], ssv[1]);
        xt[p]    = mu2[p];
        err2[p]  = pk(0.0f, 0.0f);
    }

    const u64 dt2  = pk(DTC, DTC);
    const u64 one2 = pk(1.0f, 1.0f);

    const u64* nzp = (const u64*)(noise + ((size_t)l * NSTEPS * BATCH + b) * LATENT);
    const int  nz_stride = BATCH * LATENT / 2;

    for (int s = 0; s < NSTEPS; s++) {
        // prefetch this step's noise early (hide LDG under the MLP)
        u64 nz[5];
#pragma unroll
        for (int p = 0; p < 5; p++) nz[p] = nzp[p];
        nzp += nz_stride;

        // duplicated features xd[k] = (x_k, x_k)
        u64 xd[12];
#pragma unroll
        for (int p = 0; p < 5; p++) {
            float x0, x1;
            upk(xt[p], x0, x1);
            xd[2 * p]     = pk(x0, x0);
            xd[2 * p + 1] = pk(x1, x1);
        }
        const float t = (float)(l + s) * DTC;
        xd[10] = pk(t, t);
        xd[11] = one2;

        u64 sc2[10];
#pragma unroll
        for (int e = 0; e < 10; e++) sc2[e] = b2h[e];

#pragma unroll 4
        for (int jp = 0; jp < 32; jp++) {
            const u64* w1 = sW1p[jp];
            u64 acc = mul2_(xd[0], w1[0]);
#pragma unroll
            for (int k = 1; k < 12; k++)
                acc = fma2_(xd[k], w1[k], acc);

            float h0, h1;
            upk(acc, h0, h1);
            u64 h2 = pk(fmaxf(h0, 0.0f), fmaxf(h1, 0.0f));

            const u64* w2 = sW2p[jp];
#pragma unroll
            for (int e = 0; e < 10; e++)
                sc2[e] = fma2_(h2, w2[e], sc2[e]);
        }

        // horizontal-reduce layer-2 pairs into latent d-pairs
        u64 sc[5];
#pragma unroll
        for (int p = 0; p < 5; p++) {
            float a0, a1, c0, c1;
            upk(sc2[2 * p],     a0, a1);
            upk(sc2[2 * p + 1], c0, c1);
            sc[p] = pk(a0 + a1, c0 + c1);
        }

        // elementwise SDE update + score error
#pragma unroll
        for (int p = 0; p < 5; p++) {
            u64 logdx = mul2_(sub2_(mu2[p], xt[p]), sinv2[p]);
            u64 diff  = sub2_(logdx, sc[p]);
            err2[p]   = fma2_(diff, diff, err2[p]);
            u64 x     = fma2_(mu2[p], dt2, xt[p]);     // + mu*dt
            x         = fma2_(sc[p], hv2[p], x);       // + 0.5*var*score*dt
            xt[p]     = fma2_(nz[p], ssd2[p], x);      // + sstd*sqrt(dt)*dW
        }
    }

    // ---- outputs ----
    float2* o0 = (float2*)(out + ((size_t)b * MAXLEN + l) * LATENT);
    float2* o1 = (float2*)(out + (size_t)BATCH * MAXLEN * LATENT
                               + ((size_t)b * MAXLEN + l) * LATENT);
    const float inv_n = 1.0f / (float)NSTEPS;
#pragma unroll
    for (int p = 0; p < 5; p++) {
        float x, y;
        upk(xt[p], x, y);
        o0[p] = make_float2(x, y);
        upk(err2[p], x, y);
        o1[p] = make_float2(x * inv_n, y * inv_n);
    }
}

extern "C" void kernel_launch(void* const* d_in, const int* in_sizes, int n_in,
                              void* d_out, int out_size)
{
    const float* zm    = (const float*)d_in[0];
    const float* zlv   = (const float*)d_in[1];
    const float* W1    = (const float*)d_in[2];
    const float* b1    = (const float*)d_in[3];
    const float* W2    = (const float*)d_in[4];
    const float* b2    = (const float*)d_in[5];
    const float* noise = (const float*)d_in[6];
    float* out = (float*)d_out;

    const int total = BATCH * MAXLEN;            // 40960 chains, 1 per thread
    vae_sde3_kernel<<<total / 32, 32>>>(zm, zlv, W1, b1, W2, b2, noise, out);
}

// round 6
// speedup vs baseline: 1.4118x; 1.0111x over previous
#include <cuda_runtime.h>

#define LATENT  10
#define MAXLEN  80
#define BATCH   512
#define NSTEPS  100
#define HID     64
#define DTC     0.01f

typedef unsigned long long u64;

// ---------------- packed f32x2 helpers (sm_100+) ----------------
__device__ __forceinline__ u64 pk(float x, float y) {
    u64 r;
    asm("mov.b64 %0, {%1, %2};" : "=l"(r) : "f"(x), "f"(y));
    return r;
}
__device__ __forceinline__ void upk(u64 a, float& x, float& y) {
    asm("mov.b64 {%0, %1}, %2;" : "=f"(x), "=f"(y) : "l"(a));
}
__device__ __forceinline__ u64 fma2_(u64 a, u64 b, u64 c) {
    u64 d;
    asm("fma.rn.f32x2 %0, %1, %2, %3;" : "=l"(d) : "l"(a), "l"(b), "l"(c));
    return d;
}
__device__ __forceinline__ u64 mul2_(u64 a, u64 b) {
    u64 d;
    asm("mul.rn.f32x2 %0, %1, %2;" : "=l"(d) : "l"(a), "l"(b));
    return d;
}
__device__ __forceinline__ u64 sub2_(u64 a, u64 b) {
    u64 d;
    asm("sub.rn.f32x2 %0, %1, %2;" : "=l"(d) : "l"(a), "l"(b));
    return d;
}

// Two threads per chain: lane and lane^16 share chain (lane & 15).
// Each half computes 16 of the 32 hidden-unit pairs; partial layer-2 scores
// are combined with shfl.xor(16). Both halves redundantly run the SDE update
// so xt stays register-resident in both for the next step's features.
__global__ void __launch_bounds__(32)
vae_sde4_kernel(const float* __restrict__ zm,
                const float* __restrict__ zlv,
                const float* __restrict__ W1,
                const float* __restrict__ b1,
                const float* __restrict__ W2,
                const float* __restrict__ b2,
                const float* __restrict__ noise,
                float* __restrict__ out)
{
    __shared__ __align__(16) u64 sW1p[32][12];   // (W1[k][2jp], W1[k][2jp+1]), k=11 -> b1 pair
    __shared__ __align__(16) u64 sW2p[32][10];   // (W2[2jp][e], W2[2jp+1][e])

    const int lane = threadIdx.x;                // 0..31
    const int half = lane >> 4;                  // 0 or 1
    const int ci   = lane & 15;                  // chain slot in warp

    // stage weights (each lane stages one jp)
    {
        int jp = lane;
        int j0 = 2 * jp, j1 = 2 * jp + 1;
#pragma unroll
        for (int k = 0; k < 11; k++)
            sW1p[jp][k] = pk(W1[k * HID + j0], W1[k * HID + j1]);
        sW1p[jp][11] = pk(b1[j0], b1[j1]);
#pragma unroll
        for (int e = 0; e < 10; e++)
            sW2p[jp][e] = pk(W2[j0 * 10 + e], W2[j1 * 10 + e]);
    }
    __syncwarp();

    const int chain = blockIdx.x * 16 + ci;      // < 40960
    const int l = chain >> 9;                    // uniform across warp (16 | 512)
    const int b = chain & 511;

    // layer-2 accumulator init: half 0 carries b2, half 1 zero (avoid double count)
    u64 b2h[10];
#pragma unroll
    for (int e = 0; e < 10; e++)
        b2h[e] = (half == 0) ? pk(b2[e], 0.0f) : 0ULL;

    // ---- per-chain precompute (duplicated in both halves) ----
    const float* zmr = zm  + ((size_t)b * MAXLEN + l) * LATENT;
    const float* zvr = zlv + ((size_t)b * MAXLEN + l) * LATENT;

    u64 xt[5], mu2[5], sinv2[5], hv2[5], ssd2[5], err2[5];
#pragma unroll
    for (int p = 0; p < 5; p++) {
        float muv[2], siv[2], hvv[2], ssv[2];
#pragma unroll
        for (int q = 0; q < 2; q++) {
            int d = 2 * p + q;
            float zmc = zmr[d];
            float zmp = (l > 0) ? zmr[d - LATENT] : 0.0f;
            float mu  = zmc - zmp;
            float a_  = (l > 0) ? zvr[d - LATENT] : 0.0f;
            float bb  = zvr[d];
            float mx  = fmaxf(a_, bb);
            float sg  = mx + log1pf(expf(-fabsf(a_ - bb)));   // logaddexp
            float sstd = expf(0.5f * sg);
            float svar = sstd * sstd;
            muv[q] = mu;
            siv[q] = 1.0f / sg;
            hvv[q] = 0.5f * svar * DTC;
            ssv[q] = sstd * 0.1f;          // sigma_std * sqrt(dt)
        }
        mu2[p]   = pk(muv[0], muv[1]);
        sinv2[p] = pk(siv[0], siv[1]);
        hv2[p]   = pk(hvv[0], hvv[1]);
        ssd2[p]  = pk(ssv[0], ssv[1]);
        xt[p]    = mu2[p];
        err2[p]  = pk(0.0f, 0.0f);
    }

    const u64 dt2  = pk(DTC, DTC);
    const u64 one2 = pk(1.0f, 1.0f);

    const u64* nzp = (const u64*)(noise + ((size_t)l * NSTEPS * BATCH + b) * LATENT);
    const int  nz_stride = BATCH * LATENT / 2;

    const int jp0 = half * 16;

    for (int s = 0; s < NSTEPS; s++) {
        // prefetch noise (broadcast across halves)
        u64 nz[5];
#pragma unroll
        for (int p = 0; p < 5; p++) nz[p] = nzp[p];
        nzp += nz_stride;

        // duplicated features
        u64 xd[12];
#pragma unroll
        for (int p = 0; p < 5; p++) {
            float x0, x1;
            upk(xt[p], x0, x1);
            xd[2 * p]     = pk(x0, x0);
            xd[2 * p + 1] = pk(x1, x1);
        }
        const float t = (float)(l + s) * DTC;
        xd[10] = pk(t, t);
        xd[11] = one2;

        u64 sc2[10];
#pragma unroll
        for (int e = 0; e < 10; e++) sc2[e] = b2h[e];

#pragma unroll 4
        for (int jj = 0; jj < 16; jj++) {
            const u64* w1 = sW1p[jp0 + jj];
            u64 acc = mul2_(xd[0], w1[0]);
#pragma unroll
            for (int k = 1; k < 12; k++)
                acc = fma2_(xd[k], w1[k], acc);

            float h0, h1;
            upk(acc, h0, h1);
            u64 h2 = pk(fmaxf(h0, 0.0f), fmaxf(h1, 0.0f));

            const u64* w2 = sW2p[jp0 + jj];
#pragma unroll
            for (int e = 0; e < 10; e++)
                sc2[e] = fma2_(h2, w2[e], sc2[e]);
        }

        // pair-reduce + cross-half reduce -> full score in both halves
        u64 sc[5];
#pragma unroll
        for (int p = 0; p < 5; p++) {
            float a0, a1, c0, c1;
            upk(sc2[2 * p],     a0, a1);
            upk(sc2[2 * p + 1], c0, c1);
            float x = a0 + a1;
            float y = c0 + c1;
            x += __shfl_xor_sync(0xffffffffu, x, 16);
            y += __shfl_xor_sync(0xffffffffu, y, 16);
            sc[p] = pk(x, y);
        }

        // SDE update + score error (both halves)
#pragma unroll
        for (int p = 0; p < 5; p++) {
            u64 logdx = mul2_(sub2_(mu2[p], xt[p]), sinv2[p]);
            u64 diff  = sub2_(logdx, sc[p]);
            err2[p]   = fma2_(diff, diff, err2[p]);
            u64 x     = fma2_(mu2[p], dt2, xt[p]);
            x         = fma2_(sc[p], hv2[p], x);
            xt[p]     = fma2_(nz[p], ssd2[p], x);
        }
    }

    // ---- outputs (half 0 only) ----
    if (half == 0) {
        float2* o0 = (float2*)(out + ((size_t)b * MAXLEN + l) * LATENT);
        float2* o1 = (float2*)(out + (size_t)BATCH * MAXLEN * LATENT
                                   + ((size_t)b * MAXLEN + l) * LATENT);
        const float inv_n = 1.0f / (float)NSTEPS;
#pragma unroll
        for (int p = 0; p < 5; p++) {
            float x, y;
            upk(xt[p], x, y);
            o0[p] = make_float2(x, y);
            upk(err2[p], x, y);
            o1[p] = make_float2(x * inv_n, y * inv_n);
        }
    }
}

extern "C" void kernel_launch(void* const* d_in, const int* in_sizes, int n_in,
                              void* d_out, int out_size)
{
    const float* zm    = (const float*)d_in[0];
    const float* zlv   = (const float*)d_in[1];
    const float* W1    = (const float*)d_in[2];
    const float* b1    = (const float*)d_in[3];
    const float* W2    = (const float*)d_in[4];
    const float* b2    = (const float*)d_in[5];
    const float* noise = (const float*)d_in[6];
    float* out = (float*)d_out;

    const int nblocks = BATCH * MAXLEN / 16;     // 2560 CTAs, 16 chains each (2 thr/chain)
    vae_sde4_kernel<<<nblocks, 32>>>(zm, zlv, W1, b1, W2, b2, noise, out);
}